// round 11
// baseline (speedup 1.0000x reference)
#include <cuda_runtime.h>
#include <cuda_fp16.h>

// ---------------------------------------------------------------------------
// HexPlane feature sampling, R11.
//  1) transpose_zero: tables -> fp16 channel-interleaved (3,H,W,C) + zero hist.
//  2) counting sort per plane (6x): 14-bit Morton key (128x128 grid).
//     hist -> scan_blocks/scan_tops/add_offs -> scatter (SoA: float2 uv + id).
//  3) hex_main: block=192 (6 warps), warp w = plane w, 32 sorted points/warp,
//     per-level early smem staging (low regs -> higher occupancy),
//     coalesced float4 streaming stores.
// ---------------------------------------------------------------------------

#define TAB_TOTAL 1098240
#define NMAX 1048576
#define NBUCK 16384          // 14-bit key: 128x128 Morton grid
#define NSCANBLK 192         // 6*NBUCK / 512

static __device__ __align__(16) __half g_tab[TAB_TOTAL];
static __device__ int    g_hist[6 * NBUCK];
static __device__ int    g_bsum[NSCANBLK];
static __device__ __align__(16) float2 g_uv[6 * NMAX];
static __device__ int    g_id[6 * NMAX];

struct TabSrc { const float* p[8]; };

__constant__ int c_segoff[9] = {0, 6144, 30720, 129024, 522240,
                                560640, 637440, 791040, 1098240};
__constant__ int c_seghw[8]  = {256, 1024, 4096, 16384,
                                1600, 3200, 6400, 12800};

__global__ void transpose_zero(TabSrc s) {
    int i = blockIdx.x * blockDim.x + threadIdx.x;
    if (i < 6 * NBUCK) g_hist[i] = 0;
    if (i >= TAB_TOTAL) return;
    int seg = 0;
    #pragma unroll
    for (int k = 1; k < 8; k++) seg += (i >= c_segoff[k]);
    int loc = i - c_segoff[seg];
    int HW  = c_seghw[seg];
    int c   = loc & 7;
    int r   = loc >> 3;
    int pix = r % HW;
    int pl  = r / HW;
    g_tab[i] = __float2half_rn(s.p[seg][(pl * 8 + c) * HW + pix]);
}

// ---- sorting machinery -----------------------------------------------------

__device__ __forceinline__ unsigned part1by1(unsigned x) {
    x &= 0x7F;
    x = (x | (x << 4)) & 0x0F0F;
    x = (x | (x << 2)) & 0x3333;
    x = (x | (x << 1)) & 0x5555;
    return x;
}

__device__ __forceinline__ void plane_uv(int pl, float x, float y, float z,
                                         float t, float& u, float& v) {
    // gu per plane: {x, x, y, t, t, t}; gv per plane: {y, z, z, x, y, z}
    u = pl < 3 ? (pl == 2 ? y : x) : t;
    v = (pl == 0 || pl == 4) ? y : (pl == 3 ? x : z);
}

__device__ __forceinline__ int key14(float u, float v) {
    int ku = min(127, (int)(__saturatef(u) * 128.0f));
    int kv = min(127, (int)(__saturatef(v) * 128.0f));
    return (int)(part1by1(ku) | (part1by1(kv) << 1));
}

__device__ __forceinline__ void norm_pt(const float* xyz, const float* tarr,
                                        const float* bounds, int p,
                                        float& xn, float& yn, float& zn,
                                        float& tn) {
    float b0 = __ldg(bounds + 0), b1 = __ldg(bounds + 1), b2 = __ldg(bounds + 2);
    float b3 = __ldg(bounds + 3), b4 = __ldg(bounds + 4), b5 = __ldg(bounds + 5);
    xn = __fdividef(__ldg(xyz + 3 * p + 0) - b0, b3 - b0);
    yn = __fdividef(__ldg(xyz + 3 * p + 1) - b1, b4 - b1);
    zn = __fdividef(__ldg(xyz + 3 * p + 2) - b2, b5 - b2);
    tn = __ldg(tarr + p);
}

__global__ void hist_k(const float* __restrict__ xyz,
                       const float* __restrict__ tarr,
                       const float* __restrict__ bounds, int N) {
    int p = blockIdx.x * blockDim.x + threadIdx.x;
    if (p >= N) return;
    float xn, yn, zn, tn;
    norm_pt(xyz, tarr, bounds, p, xn, yn, zn, tn);
    #pragma unroll
    for (int pl = 0; pl < 6; pl++) {
        float u, v;
        plane_uv(pl, xn, yn, zn, tn, u, v);
        atomicAdd(&g_hist[pl * NBUCK + key14(u, v)], 1);
    }
}

// Phase 1: block-local exclusive scan of 512 buckets; emit block total.
__global__ void scan_blocks() {
    __shared__ int sm[512];
    int gbase = blockIdx.x * 512;
    int tid = threadIdx.x;
    int v = g_hist[gbase + tid];
    sm[tid] = v;
    __syncthreads();
    #pragma unroll
    for (int off = 1; off < 512; off <<= 1) {
        int t = (tid >= off) ? sm[tid - off] : 0;
        __syncthreads();
        sm[tid] += t;
        __syncthreads();
    }
    g_hist[gbase + tid] = sm[tid] - v;   // exclusive
    if (tid == 511) g_bsum[blockIdx.x] = sm[511];
}

// Phase 2: per-plane exclusive scan of the 32 block sums (6 warps).
__global__ void scan_tops() {
    int w = threadIdx.x >> 5, lane = threadIdx.x & 31;
    if (w < 6) {
        int i = w * 32 + lane;
        int v = g_bsum[i];
        int s = v;
        #pragma unroll
        for (int off = 1; off < 32; off <<= 1) {
            int t = __shfl_up_sync(0xffffffffu, s, off);
            if (lane >= off) s += t;
        }
        g_bsum[i] = s - v;
    }
}

// Phase 3: add block offsets.
__global__ void add_offs() {
    int i = blockIdx.x * blockDim.x + threadIdx.x;
    if (i < 6 * NBUCK) g_hist[i] += g_bsum[i >> 9];
}

__global__ void scatter_k(const float* __restrict__ xyz,
                          const float* __restrict__ tarr,
                          const float* __restrict__ bounds, int N) {
    int p = blockIdx.x * blockDim.x + threadIdx.x;
    if (p >= N) return;
    float xn, yn, zn, tn;
    norm_pt(xyz, tarr, bounds, p, xn, yn, zn, tn);
    #pragma unroll
    for (int pl = 0; pl < 6; pl++) {
        float u, v;
        plane_uv(pl, xn, yn, zn, tn, u, v);
        int pos = atomicAdd(&g_hist[pl * NBUCK + key14(u, v)], 1);
        g_uv[pl * NMAX + pos] = make_float2(u, v);
        g_id[pl * NMAX + pos] = p;
    }
}

// ---- main sampling kernel ---------------------------------------------------

__device__ __forceinline__ void unpack_texel(float4 raw, float* v) {
    const __half2* h = (const __half2*)&raw;
    #pragma unroll
    for (int k = 0; k < 4; k++) {
        float2 f = __half22float2(h[k]);
        v[2 * k]     = f.x;
        v[2 * k + 1] = f.y;
    }
}

__global__ __launch_bounds__(192, 5) void hex_main(float* __restrict__ out,
                                                   int N) {
    __shared__ float4 stage[6][32][9];   // stride 9 f4: conflict-free
    int w    = threadIdx.x >> 5;         // plane (warp-uniform)
    int lane = threadIdx.x & 31;
    long tilebase = (long)blockIdx.x * 32;
    int  idx = (int)tilebase + lane;
    bool act = idx < N;

    float u = 0.0f, v = 0.0f;
    int p = 0;
    if (act) {
        float2 pr = __ldg(&g_uv[w * NMAX + idx]);
        u = pr.x; v = pr.y;
        p = __ldg(&g_id[w * NMAX + idx]);
    }
    bool sp = w < 3;

    const int SPOFF[4] = {0, 6144, 30720, 129024};
    const int TPOFF[4] = {522240, 560640, 637440, 791040};

    #pragma unroll
    for (int l = 0; l < 4; l++) {
        const int R = 16 << l;
        const int W = sp ? R : 100;
        const int H = R;
        float fW = (float)W, fH = (float)H;

        // spatial: align_corners=false ; temporal: align_corners=true
        float ix = sp ? fmaf(u, fW, -0.5f) : u * (fW - 1.0f);
        float iy = sp ? fmaf(v, fH, -0.5f) : v * (fH - 1.0f);
        ix = fminf(fmaxf(ix, 0.0f), fW - 1.0f);
        iy = fminf(fmaxf(iy, 0.0f), fH - 1.0f);

        float x0f = floorf(ix);
        float y0f = floorf(iy);
        float wx = ix - x0f;
        float wy = iy - y0f;
        int x0 = (int)x0f;
        int y0 = (int)y0f;
        int x1 = min(x0 + 1, W - 1);
        int y1 = min(y0 + 1, H - 1);

        const __half* baseh = g_tab +
            (sp ? (SPOFF[l] + w * 8 * R * R)
                : (TPOFF[l] + (w - 3) * 8 * R * 100));
        const float4* bp = (const float4*)baseh;

        int row0 = y0 * W;
        int row1 = y1 * W;

        float v00[8], v01[8], v10[8], v11[8];
        unpack_texel(__ldg(bp + row0 + x0), v00);
        unpack_texel(__ldg(bp + row0 + x1), v01);
        unpack_texel(__ldg(bp + row1 + x0), v10);
        unpack_texel(__ldg(bp + row1 + x1), v11);

        float res[8];
        #pragma unroll
        for (int c = 0; c < 8; c++) {
            float top = fmaf(wx, v01[c] - v00[c], v00[c]);
            float bot = fmaf(wx, v11[c] - v10[c], v10[c]);
            res[c] = fmaf(wy, bot - top, top);
        }
        // early staging (keeps register count low)
        stage[w][lane][2 * l]     = make_float4(res[0], res[1], res[2], res[3]);
        stage[w][lane][2 * l + 1] = make_float4(res[4], res[5], res[6], res[7]);
    }
    __syncwarp();

    // cooperative write-out: round r covers points r*4..r*4+3, 8 f4 each.
    float4* out4 = (float4*)out;
    #pragma unroll
    for (int r = 0; r < 8; r++) {
        int pt = r * 4 + (lane >> 3);
        int c4 = lane & 7;
        int pp = __shfl_sync(0xffffffffu, p, pt);
        float4 val = stage[w][pt][c4];
        if (tilebase + pt < N)
            __stcs(out4 + (long)pp * 48 + w * 8 + c4, val);
    }
}

// ---- host glue ---------------------------------------------------------------

extern "C" void kernel_launch(void* const* d_in, const int* in_sizes, int n_in,
                              void* d_out, int out_size) {
    const float* xyz    = (const float*)d_in[0];
    const float* tarr   = (const float*)d_in[1];
    const float* bounds = (const float*)d_in[2];

    int N = in_sizes[0] / 3;

    // Identify table inputs BY SIZE (dataset dict interleaves sp_i / tp_i).
    TabSrc src{};
    for (int j = 3; j < n_in; j++) {
        const float* ptr = (const float*)d_in[j];
        switch (in_sizes[j]) {
            case 6144:   src.p[0] = ptr; break;  // sp0
            case 24576:  src.p[1] = ptr; break;  // sp1
            case 98304:  src.p[2] = ptr; break;  // sp2
            case 393216: src.p[3] = ptr; break;  // sp3
            case 38400:  src.p[4] = ptr; break;  // tp0
            case 76800:  src.p[5] = ptr; break;  // tp1
            case 153600: src.p[6] = ptr; break;  // tp2
            case 307200: src.p[7] = ptr; break;  // tp3
            default: break;
        }
    }

    transpose_zero<<<(TAB_TOTAL + 255) / 256, 256>>>(src);
    hist_k<<<(N + 255) / 256, 256>>>(xyz, tarr, bounds, N);
    scan_blocks<<<NSCANBLK, 512>>>();
    scan_tops<<<1, 192>>>();
    add_offs<<<(6 * NBUCK + 1023) / 1024, 1024>>>();
    scatter_k<<<(N + 255) / 256, 256>>>(xyz, tarr, bounds, N);

    hex_main<<<(N + 31) / 32, 192>>>((float*)d_out, N);
}

// round 12
// speedup vs baseline: 1.0872x; 1.0872x over previous
#include <cuda_runtime.h>
#include <cuda_fp16.h>

// ---------------------------------------------------------------------------
// HexPlane feature sampling, R12.
//  Launches (4): hist_transpose -> scan_all -> scatter_k -> hex_main.
//  - hist_transpose: grid-partitioned: first HB blocks histogram 14-bit Morton
//    keys (6 planes/point); remaining blocks transpose tables into fp16
//    channel-interleaved (3,H,W,C) (texel = 16B).
//  - scan_all: one kernel. block-local exclusive scan of 512 buckets, publish
//    block sum, spin-barrier on arrival counter (192 blocks, all resident),
//    then add per-plane prefix of block sums.
//  - scatter_k: writes sorted records g_pt = (u, v, id) per plane.
//  - hex_main (== R10 fast version): block=192, warp w = plane w, 32 sorted
//    points/warp, register accumulation, warp smem staging, coalesced stores.
//    Head re-zeroes g_hist/g_arrive for the next graph replay.
// ---------------------------------------------------------------------------

#define TAB_TOTAL 1098240
#define NMAX 1048576
#define NBUCK 16384          // 14-bit key: 128x128 Morton grid
#define NSCANBLK 192         // 6*NBUCK / 512

static __device__ __align__(16) __half g_tab[TAB_TOTAL];
static __device__ int    g_hist[6 * NBUCK];      // zero-init; re-zeroed by hex_main
static __device__ int    g_bsum[NSCANBLK];
static __device__ int    g_arrive;               // zero-init; re-zeroed by hex_main
static __device__ __align__(16) float4 g_pt[6 * NMAX];   // (u, v, bits(p), -)

struct TabSrc { const float* p[8]; };

__constant__ int c_segoff[9] = {0, 6144, 30720, 129024, 522240,
                                560640, 637440, 791040, 1098240};
__constant__ int c_seghw[8]  = {256, 1024, 4096, 16384,
                                1600, 3200, 6400, 12800};

// ---- helpers ----------------------------------------------------------------

__device__ __forceinline__ unsigned part1by1(unsigned x) {
    x &= 0x7F;
    x = (x | (x << 4)) & 0x0F0F;
    x = (x | (x << 2)) & 0x3333;
    x = (x | (x << 1)) & 0x5555;
    return x;
}

__device__ __forceinline__ void plane_uv(int pl, float x, float y, float z,
                                         float t, float& u, float& v) {
    // gu per plane: {x, x, y, t, t, t}; gv per plane: {y, z, z, x, y, z}
    u = pl < 3 ? (pl == 2 ? y : x) : t;
    v = (pl == 0 || pl == 4) ? y : (pl == 3 ? x : z);
}

__device__ __forceinline__ int key14(float u, float v) {
    int ku = min(127, (int)(__saturatef(u) * 128.0f));
    int kv = min(127, (int)(__saturatef(v) * 128.0f));
    return (int)(part1by1(ku) | (part1by1(kv) << 1));
}

__device__ __forceinline__ void norm_pt(const float* xyz, const float* tarr,
                                        const float* bounds, int p,
                                        float& xn, float& yn, float& zn,
                                        float& tn) {
    float b0 = __ldg(bounds + 0), b1 = __ldg(bounds + 1), b2 = __ldg(bounds + 2);
    float b3 = __ldg(bounds + 3), b4 = __ldg(bounds + 4), b5 = __ldg(bounds + 5);
    xn = __fdividef(__ldg(xyz + 3 * p + 0) - b0, b3 - b0);
    yn = __fdividef(__ldg(xyz + 3 * p + 1) - b1, b4 - b1);
    zn = __fdividef(__ldg(xyz + 3 * p + 2) - b2, b5 - b2);
    tn = __ldg(tarr + p);
}

// ---- launch 0: fused histogram + table transpose ------------------------------

__global__ void hist_transpose(const float* __restrict__ xyz,
                               const float* __restrict__ tarr,
                               const float* __restrict__ bounds,
                               TabSrc s, int N, int HB) {
    if ((int)blockIdx.x < HB) {
        int p = blockIdx.x * 256 + threadIdx.x;
        if (p >= N) return;
        float xn, yn, zn, tn;
        norm_pt(xyz, tarr, bounds, p, xn, yn, zn, tn);
        #pragma unroll
        for (int pl = 0; pl < 6; pl++) {
            float u, v;
            plane_uv(pl, xn, yn, zn, tn, u, v);
            atomicAdd(&g_hist[pl * NBUCK + key14(u, v)], 1);
        }
    } else {
        int i = (blockIdx.x - HB) * 256 + threadIdx.x;
        if (i >= TAB_TOTAL) return;
        int seg = 0;
        #pragma unroll
        for (int k = 1; k < 8; k++) seg += (i >= c_segoff[k]);
        int loc = i - c_segoff[seg];
        int HW  = c_seghw[seg];
        int c   = loc & 7;
        int r   = loc >> 3;
        int pix = r % HW;
        int pl  = r / HW;
        g_tab[i] = __float2half_rn(s.p[seg][(pl * 8 + c) * HW + pix]);
    }
}

// ---- launch 1: single-kernel scan (block scan + spin barrier + prefix) --------

__global__ void scan_all() {
    __shared__ int sm[512];
    int bid = blockIdx.x;
    int tid = threadIdx.x;
    int gbase = bid * 512;

    int v = g_hist[gbase + tid];
    sm[tid] = v;
    __syncthreads();
    #pragma unroll
    for (int off = 1; off < 512; off <<= 1) {
        int t = (tid >= off) ? sm[tid - off] : 0;
        __syncthreads();
        sm[tid] += t;
        __syncthreads();
    }
    int local_excl = sm[tid] - v;

    if (tid == 0) {
        g_bsum[bid] = sm[511];
        __threadfence();
        atomicAdd(&g_arrive, 1);
        while (atomicAdd(&g_arrive, 0) < NSCANBLK) { }
        __threadfence();
    }
    __syncthreads();

    // per-plane prefix of block sums: plane = bid/32
    int pstart = (bid >> 5) << 5;
    int off = 0;
    for (int j = pstart; j < bid; j++) off += g_bsum[j];
    g_hist[gbase + tid] = local_excl + off;
}

// ---- launch 2: scatter ---------------------------------------------------------

__global__ void scatter_k(const float* __restrict__ xyz,
                          const float* __restrict__ tarr,
                          const float* __restrict__ bounds, int N) {
    int p = blockIdx.x * blockDim.x + threadIdx.x;
    if (p >= N) return;
    float xn, yn, zn, tn;
    norm_pt(xyz, tarr, bounds, p, xn, yn, zn, tn);
    #pragma unroll
    for (int pl = 0; pl < 6; pl++) {
        float u, v;
        plane_uv(pl, xn, yn, zn, tn, u, v);
        int pos = atomicAdd(&g_hist[pl * NBUCK + key14(u, v)], 1);
        g_pt[pl * NMAX + pos] = make_float4(u, v, __int_as_float(p), 0.0f);
    }
}

// ---- launch 3: main sampling kernel (R10 version + state re-arm) ---------------

__device__ __forceinline__ void unpack_texel(float4 raw, float* v) {
    const __half2* h = (const __half2*)&raw;
    #pragma unroll
    for (int k = 0; k < 4; k++) {
        float2 f = __half22float2(h[k]);
        v[2 * k]     = f.x;
        v[2 * k + 1] = f.y;
    }
}

__global__ __launch_bounds__(192) void hex_main(float* __restrict__ out, int N) {
    // re-arm sort state for the next graph replay (hist/arrive no longer needed
    // this call: scan+scatter already consumed them).
    {
        int gid = blockIdx.x * 192 + threadIdx.x;
        if (gid < 6 * NBUCK) g_hist[gid] = 0;
        if (gid == 6 * NBUCK) g_arrive = 0;
    }

    __shared__ float4 stage[6][32][9];   // stride 9 f4: conflict-free
    int w    = threadIdx.x >> 5;         // plane (warp-uniform)
    int lane = threadIdx.x & 31;
    long tilebase = (long)blockIdx.x * 32;
    int  idx = (int)tilebase + lane;
    bool act = idx < N;

    float u = 0.0f, v = 0.0f;
    int p = 0;
    if (act) {
        float4 pr = __ldg(&g_pt[w * NMAX + idx]);
        u = pr.x; v = pr.y; p = __float_as_int(pr.z);
    }
    bool sp = w < 3;

    const int SPOFF[4] = {0, 6144, 30720, 129024};
    const int TPOFF[4] = {522240, 560640, 637440, 791040};

    float4 r4[8];
    #pragma unroll
    for (int l = 0; l < 4; l++) {
        const int R = 16 << l;
        const int W = sp ? R : 100;
        const int H = R;
        float fW = (float)W, fH = (float)H;

        // spatial: align_corners=false ; temporal: align_corners=true
        float ix = sp ? fmaf(u, fW, -0.5f) : u * (fW - 1.0f);
        float iy = sp ? fmaf(v, fH, -0.5f) : v * (fH - 1.0f);
        ix = fminf(fmaxf(ix, 0.0f), fW - 1.0f);
        iy = fminf(fmaxf(iy, 0.0f), fH - 1.0f);

        float x0f = floorf(ix);
        float y0f = floorf(iy);
        float wx = ix - x0f;
        float wy = iy - y0f;
        int x0 = (int)x0f;
        int y0 = (int)y0f;
        int x1 = min(x0 + 1, W - 1);
        int y1 = min(y0 + 1, H - 1);

        const __half* baseh = g_tab +
            (sp ? (SPOFF[l] + w * 8 * R * R)
                : (TPOFF[l] + (w - 3) * 8 * R * 100));
        const float4* bp = (const float4*)baseh;

        int row0 = y0 * W;
        int row1 = y1 * W;

        float v00[8], v01[8], v10[8], v11[8];
        unpack_texel(__ldg(bp + row0 + x0), v00);
        unpack_texel(__ldg(bp + row0 + x1), v01);
        unpack_texel(__ldg(bp + row1 + x0), v10);
        unpack_texel(__ldg(bp + row1 + x1), v11);

        float res[8];
        #pragma unroll
        for (int c = 0; c < 8; c++) {
            float top = fmaf(wx, v01[c] - v00[c], v00[c]);
            float bot = fmaf(wx, v11[c] - v10[c], v10[c]);
            res[c] = fmaf(wy, bot - top, top);
        }
        r4[2 * l]     = make_float4(res[0], res[1], res[2], res[3]);
        r4[2 * l + 1] = make_float4(res[4], res[5], res[6], res[7]);
    }

    // warp-local stage (no block barrier needed)
    #pragma unroll
    for (int j = 0; j < 8; j++) stage[w][lane][j] = r4[j];
    __syncwarp();

    // cooperative write-out: round r covers points r*4..r*4+3, 8 f4 each.
    float4* out4 = (float4*)out;
    #pragma unroll
    for (int r = 0; r < 8; r++) {
        int pt = r * 4 + (lane >> 3);
        int c4 = lane & 7;
        int pp = __shfl_sync(0xffffffffu, p, pt);
        float4 val = stage[w][pt][c4];
        if (tilebase + pt < N)
            __stcs(out4 + (long)pp * 48 + w * 8 + c4, val);
    }
}

// ---- host glue ---------------------------------------------------------------

extern "C" void kernel_launch(void* const* d_in, const int* in_sizes, int n_in,
                              void* d_out, int out_size) {
    const float* xyz    = (const float*)d_in[0];
    const float* tarr   = (const float*)d_in[1];
    const float* bounds = (const float*)d_in[2];

    int N = in_sizes[0] / 3;

    // Identify table inputs BY SIZE (dataset dict interleaves sp_i / tp_i).
    TabSrc src{};
    for (int j = 3; j < n_in; j++) {
        const float* ptr = (const float*)d_in[j];
        switch (in_sizes[j]) {
            case 6144:   src.p[0] = ptr; break;  // sp0
            case 24576:  src.p[1] = ptr; break;  // sp1
            case 98304:  src.p[2] = ptr; break;  // sp2
            case 393216: src.p[3] = ptr; break;  // sp3
            case 38400:  src.p[4] = ptr; break;  // tp0
            case 76800:  src.p[5] = ptr; break;  // tp1
            case 153600: src.p[6] = ptr; break;  // tp2
            case 307200: src.p[7] = ptr; break;  // tp3
            default: break;
        }
    }

    int HB = (N + 255) / 256;
    int TB = (TAB_TOTAL + 255) / 256;

    hist_transpose<<<HB + TB, 256>>>(xyz, tarr, bounds, src, N, HB);
    scan_all<<<NSCANBLK, 512>>>();
    scatter_k<<<(N + 255) / 256, 256>>>(xyz, tarr, bounds, N);
    hex_main<<<(N + 31) / 32, 192>>>((float*)d_out, N);
}

// round 13
// speedup vs baseline: 1.2201x; 1.1222x over previous
#include <cuda_runtime.h>
#include <cuda_fp16.h>

// ---------------------------------------------------------------------------
// HexPlane feature sampling, R13.
//  Launches (4): hist_transpose -> scan_all -> scatter_k -> hex_main.
//  - sort records packed into 8B: u:22 | v:22 | id:20  (halves scatter-store
//    and hex_main record-read traffic vs R12's float4 records).
//  - hist_transpose: fused histogram (14-bit per-plane Morton) + fp16
//    channel-interleaved table transpose.
//  - scan_all: block scan + resident spin-barrier + per-plane prefix.
//  - hex_main: block=192, warp w = plane w, 32 sorted points/warp, register
//    accumulation, warp smem staging, coalesced float4 streaming stores.
//    Head re-zeroes g_hist/g_arrive for the next graph replay.
// ---------------------------------------------------------------------------

#define TAB_TOTAL 1098240
#define NMAX 1048576
#define NBUCK 16384          // 14-bit key: 128x128 Morton grid
#define NSCANBLK 192         // 6*NBUCK / 512
#define UVSCALE 4194304.0f   // 2^22
#define UVINV   (1.0f / 4194304.0f)

static __device__ __align__(16) __half g_tab[TAB_TOTAL];
static __device__ int    g_hist[6 * NBUCK];      // zero-init; re-zeroed by hex_main
static __device__ int    g_bsum[NSCANBLK];
static __device__ int    g_arrive;               // zero-init; re-zeroed by hex_main
static __device__ __align__(16) uint2 g_rec[6 * NMAX];   // packed u|v|id

struct TabSrc { const float* p[8]; };

__constant__ int c_segoff[9] = {0, 6144, 30720, 129024, 522240,
                                560640, 637440, 791040, 1098240};
__constant__ int c_seghw[8]  = {256, 1024, 4096, 16384,
                                1600, 3200, 6400, 12800};

// ---- helpers ----------------------------------------------------------------

__device__ __forceinline__ unsigned part1by1(unsigned x) {
    x &= 0x7F;
    x = (x | (x << 4)) & 0x0F0F;
    x = (x | (x << 2)) & 0x3333;
    x = (x | (x << 1)) & 0x5555;
    return x;
}

__device__ __forceinline__ void plane_uv(int pl, float x, float y, float z,
                                         float t, float& u, float& v) {
    // gu per plane: {x, x, y, t, t, t}; gv per plane: {y, z, z, x, y, z}
    u = pl < 3 ? (pl == 2 ? y : x) : t;
    v = (pl == 0 || pl == 4) ? y : (pl == 3 ? x : z);
}

__device__ __forceinline__ int key14(float u, float v) {
    int ku = min(127, (int)(__saturatef(u) * 128.0f));
    int kv = min(127, (int)(__saturatef(v) * 128.0f));
    return (int)(part1by1(ku) | (part1by1(kv) << 1));
}

__device__ __forceinline__ void norm_pt(const float* xyz, const float* tarr,
                                        const float* bounds, int p,
                                        float& xn, float& yn, float& zn,
                                        float& tn) {
    float b0 = __ldg(bounds + 0), b1 = __ldg(bounds + 1), b2 = __ldg(bounds + 2);
    float b3 = __ldg(bounds + 3), b4 = __ldg(bounds + 4), b5 = __ldg(bounds + 5);
    xn = __fdividef(__ldg(xyz + 3 * p + 0) - b0, b3 - b0);
    yn = __fdividef(__ldg(xyz + 3 * p + 1) - b1, b4 - b1);
    zn = __fdividef(__ldg(xyz + 3 * p + 2) - b2, b5 - b2);
    tn = __ldg(tarr + p);
}

// ---- launch 0: fused histogram + table transpose ------------------------------

__global__ void hist_transpose(const float* __restrict__ xyz,
                               const float* __restrict__ tarr,
                               const float* __restrict__ bounds,
                               TabSrc s, int N, int HB) {
    if ((int)blockIdx.x < HB) {
        int p = blockIdx.x * 256 + threadIdx.x;
        if (p >= N) return;
        float xn, yn, zn, tn;
        norm_pt(xyz, tarr, bounds, p, xn, yn, zn, tn);
        #pragma unroll
        for (int pl = 0; pl < 6; pl++) {
            float u, v;
            plane_uv(pl, xn, yn, zn, tn, u, v);
            atomicAdd(&g_hist[pl * NBUCK + key14(u, v)], 1);
        }
    } else {
        int i = (blockIdx.x - HB) * 256 + threadIdx.x;
        if (i >= TAB_TOTAL) return;
        int seg = 0;
        #pragma unroll
        for (int k = 1; k < 8; k++) seg += (i >= c_segoff[k]);
        int loc = i - c_segoff[seg];
        int HW  = c_seghw[seg];
        int c   = loc & 7;
        int r   = loc >> 3;
        int pix = r % HW;
        int pl  = r / HW;
        g_tab[i] = __float2half_rn(s.p[seg][(pl * 8 + c) * HW + pix]);
    }
}

// ---- launch 1: single-kernel scan (block scan + spin barrier + prefix) --------

__global__ void scan_all() {
    __shared__ int sm[512];
    int bid = blockIdx.x;
    int tid = threadIdx.x;
    int gbase = bid * 512;

    int v = g_hist[gbase + tid];
    sm[tid] = v;
    __syncthreads();
    #pragma unroll
    for (int off = 1; off < 512; off <<= 1) {
        int t = (tid >= off) ? sm[tid - off] : 0;
        __syncthreads();
        sm[tid] += t;
        __syncthreads();
    }
    int local_excl = sm[tid] - v;

    if (tid == 0) {
        g_bsum[bid] = sm[511];
        __threadfence();
        atomicAdd(&g_arrive, 1);
        while (atomicAdd(&g_arrive, 0) < NSCANBLK) { }
        __threadfence();
    }
    __syncthreads();

    // per-plane prefix of block sums: plane = bid/32
    int pstart = (bid >> 5) << 5;
    int off = 0;
    for (int j = pstart; j < bid; j++) off += g_bsum[j];
    g_hist[gbase + tid] = local_excl + off;
}

// ---- launch 2: scatter (8B packed records) ------------------------------------

__global__ void scatter_k(const float* __restrict__ xyz,
                          const float* __restrict__ tarr,
                          const float* __restrict__ bounds, int N) {
    int p = blockIdx.x * blockDim.x + threadIdx.x;
    if (p >= N) return;
    float xn, yn, zn, tn;
    norm_pt(xyz, tarr, bounds, p, xn, yn, zn, tn);
    #pragma unroll
    for (int pl = 0; pl < 6; pl++) {
        float u, v;
        plane_uv(pl, xn, yn, zn, tn, u, v);
        int pos = atomicAdd(&g_hist[pl * NBUCK + key14(u, v)], 1);
        unsigned uq = (unsigned)fminf(__saturatef(u) * UVSCALE, UVSCALE - 1.0f);
        unsigned vq = (unsigned)fminf(__saturatef(v) * UVSCALE, UVSCALE - 1.0f);
        unsigned long long val = ((unsigned long long)uq << 42)
                               | ((unsigned long long)vq << 20)
                               | (unsigned)p;
        g_rec[pl * NMAX + pos] = make_uint2((unsigned)val, (unsigned)(val >> 32));
    }
}

// ---- launch 3: main sampling kernel -------------------------------------------

__device__ __forceinline__ void unpack_texel(float4 raw, float* v) {
    const __half2* h = (const __half2*)&raw;
    #pragma unroll
    for (int k = 0; k < 4; k++) {
        float2 f = __half22float2(h[k]);
        v[2 * k]     = f.x;
        v[2 * k + 1] = f.y;
    }
}

__global__ __launch_bounds__(192) void hex_main(float* __restrict__ out, int N) {
    // re-arm sort state for the next graph replay.
    {
        int gid = blockIdx.x * 192 + threadIdx.x;
        if (gid < 6 * NBUCK) g_hist[gid] = 0;
        if (gid == 6 * NBUCK) g_arrive = 0;
    }

    __shared__ float4 stage[6][32][9];   // stride 9 f4: conflict-free
    int w    = threadIdx.x >> 5;         // plane (warp-uniform)
    int lane = threadIdx.x & 31;
    long tilebase = (long)blockIdx.x * 32;
    int  idx = (int)tilebase + lane;
    bool act = idx < N;

    float u = 0.0f, v = 0.0f;
    int p = 0;
    if (act) {
        uint2 r = __ldg(&g_rec[w * NMAX + idx]);
        unsigned long long val = ((unsigned long long)r.y << 32) | r.x;
        p = (int)(val & 0xFFFFFu);
        v = (float)((val >> 20) & 0x3FFFFFu) * UVINV;
        u = (float)(val >> 42) * UVINV;
    }
    bool sp = w < 3;

    const int SPOFF[4] = {0, 6144, 30720, 129024};
    const int TPOFF[4] = {522240, 560640, 637440, 791040};

    float4 r4[8];
    #pragma unroll
    for (int l = 0; l < 4; l++) {
        const int R = 16 << l;
        const int W = sp ? R : 100;
        const int H = R;
        float fW = (float)W, fH = (float)H;

        // spatial: align_corners=false ; temporal: align_corners=true
        float ix = sp ? fmaf(u, fW, -0.5f) : u * (fW - 1.0f);
        float iy = sp ? fmaf(v, fH, -0.5f) : v * (fH - 1.0f);
        ix = fminf(fmaxf(ix, 0.0f), fW - 1.0f);
        iy = fminf(fmaxf(iy, 0.0f), fH - 1.0f);

        float x0f = floorf(ix);
        float y0f = floorf(iy);
        float wx = ix - x0f;
        float wy = iy - y0f;
        int x0 = (int)x0f;
        int y0 = (int)y0f;
        int x1 = min(x0 + 1, W - 1);
        int y1 = min(y0 + 1, H - 1);

        const __half* baseh = g_tab +
            (sp ? (SPOFF[l] + w * 8 * R * R)
                : (TPOFF[l] + (w - 3) * 8 * R * 100));
        const float4* bp = (const float4*)baseh;

        int row0 = y0 * W;
        int row1 = y1 * W;

        float v00[8], v01[8], v10[8], v11[8];
        unpack_texel(__ldg(bp + row0 + x0), v00);
        unpack_texel(__ldg(bp + row0 + x1), v01);
        unpack_texel(__ldg(bp + row1 + x0), v10);
        unpack_texel(__ldg(bp + row1 + x1), v11);

        float res[8];
        #pragma unroll
        for (int c = 0; c < 8; c++) {
            float top = fmaf(wx, v01[c] - v00[c], v00[c]);
            float bot = fmaf(wx, v11[c] - v10[c], v10[c]);
            res[c] = fmaf(wy, bot - top, top);
        }
        r4[2 * l]     = make_float4(res[0], res[1], res[2], res[3]);
        r4[2 * l + 1] = make_float4(res[4], res[5], res[6], res[7]);
    }

    // warp-local stage (no block barrier needed)
    #pragma unroll
    for (int j = 0; j < 8; j++) stage[w][lane][j] = r4[j];
    __syncwarp();

    // cooperative write-out: round r covers points r*4..r*4+3, 8 f4 each.
    float4* out4 = (float4*)out;
    #pragma unroll
    for (int r = 0; r < 8; r++) {
        int pt = r * 4 + (lane >> 3);
        int c4 = lane & 7;
        int pp = __shfl_sync(0xffffffffu, p, pt);
        float4 val = stage[w][pt][c4];
        if (tilebase + pt < N)
            __stcs(out4 + (long)pp * 48 + w * 8 + c4, val);
    }
}

// ---- host glue ---------------------------------------------------------------

extern "C" void kernel_launch(void* const* d_in, const int* in_sizes, int n_in,
                              void* d_out, int out_size) {
    const float* xyz    = (const float*)d_in[0];
    const float* tarr   = (const float*)d_in[1];
    const float* bounds = (const float*)d_in[2];

    int N = in_sizes[0] / 3;

    // Identify table inputs BY SIZE (dataset dict interleaves sp_i / tp_i).
    TabSrc src{};
    for (int j = 3; j < n_in; j++) {
        const float* ptr = (const float*)d_in[j];
        switch (in_sizes[j]) {
            case 6144:   src.p[0] = ptr; break;  // sp0
            case 24576:  src.p[1] = ptr; break;  // sp1
            case 98304:  src.p[2] = ptr; break;  // sp2
            case 393216: src.p[3] = ptr; break;  // sp3
            case 38400:  src.p[4] = ptr; break;  // tp0
            case 76800:  src.p[5] = ptr; break;  // tp1
            case 153600: src.p[6] = ptr; break;  // tp2
            case 307200: src.p[7] = ptr; break;  // tp3
            default: break;
        }
    }

    int HB = (N + 255) / 256;
    int TB = (TAB_TOTAL + 255) / 256;

    hist_transpose<<<HB + TB, 256>>>(xyz, tarr, bounds, src, N, HB);
    scan_all<<<NSCANBLK, 512>>>();
    scatter_k<<<(N + 255) / 256, 256>>>(xyz, tarr, bounds, N);
    hex_main<<<(N + 31) / 32, 192>>>((float*)d_out, N);
}